// round 1
// baseline (speedup 1.0000x reference)
#include <cuda_runtime.h>
#include <cuda_bf16.h>

// Pillar scatter: out[b, f, y, x] = sum over pillars p in batch b with
// contains_pillars[b,p]==1 and coord[b,p,1]==y, coord[b,p,2]==x of pillars[b,p,f].
// Output [B, NF, 512, 512] fp32. Strategy: zero-fill (HBM-bound) + atomic scatter.

#define XS 512
#define YS 512
#define GRID_CELLS (XS * YS)

__global__ void zero_kernel(float4* __restrict__ out, long n4) {
    long i = (long)blockIdx.x * blockDim.x + threadIdx.x;
    long stride = (long)gridDim.x * blockDim.x;
    float4 z = make_float4(0.f, 0.f, 0.f, 0.f);
    for (; i < n4; i += stride)
        out[i] = z;
}

__global__ void scatter_kernel(const float* __restrict__ pillars,
                               const int* __restrict__ coord,
                               const int* __restrict__ mask,
                               float* __restrict__ out,
                               int total_pillars, int P, int NF) {
    int warp_global = (int)((blockIdx.x * (long)blockDim.x + threadIdx.x) >> 5);
    int lane = threadIdx.x & 31;
    if (warp_global >= total_pillars) return;

    // Warp-uniform skip of empty pillars (~50% of work eliminated).
    if (mask[warp_global] == 0) return;

    int b = warp_global / P;
    int y = coord[warp_global * 3 + 1];
    int x = coord[warp_global * 3 + 2];
    long idx = (long)y * XS + x;

    float* base = out + (long)b * NF * GRID_CELLS + idx;
    const float* prow = pillars + (long)warp_global * NF;

    // Coalesced 256B read of the pillar's feature row; scattered 4B RED.ADD
    // writes (feature stride = 1 MB in the output). Atomics required: multiple
    // pillars can map to the same cell.
    for (int f = lane; f < NF; f += 32) {
        atomicAdd(base + (long)f * GRID_CELLS, prow[f]);
    }
}

extern "C" void kernel_launch(void* const* d_in, const int* in_sizes, int n_in,
                              void* d_out, int out_size) {
    const float* pillars = (const float*)d_in[0];   // [B, P, NF]
    const int*   coord   = (const int*)d_in[1];     // [B, P, 3]
    const int*   mask    = (const int*)d_in[2];     // [B, P]
    // d_in[3], d_in[4] are xsize/ysize scalars; compile-time 512 here.

    int BP = in_sizes[2];                 // B * P
    int NF = in_sizes[0] / BP;            // 64
    int B  = (int)((long)out_size / ((long)NF * GRID_CELLS));
    int P  = BP / B;

    float* out = (float*)d_out;

    // 1) Zero-fill 268 MB output. Grid-stride float4 stores.
    long n4 = (long)out_size / 4;
    zero_kernel<<<1184, 256>>>((float4*)out, n4);

    // 2) One warp per pillar, atomic scatter-add.
    int threads = 256;
    long total_threads = (long)BP * 32;
    int blocks = (int)((total_threads + threads - 1) / threads);
    scatter_kernel<<<blocks, threads>>>(pillars, coord, mask, out, BP, P, NF);
}